// round 3
// baseline (speedup 1.0000x reference)
#include <cuda_runtime.h>
#include <cstdint>

#define D_IN 64
#define D_EDGE 16
#define H 16
#define MAXN 102400
#define MAXE 3276800

typedef unsigned long long ull;

// ---------------- static device scratch ----------------
__device__ float g_xm[(MAXN + 16) * H];    // x @ W_msg1[:64]
__device__ float g_sk1[(MAXN + 16) * H];   // x @ W_skip1 + b_skip1
__device__ float g_agg1[(MAXN + 16) * H];  // conv1 segment sum (+sentinel row)
__device__ float g_agg2[(MAXN + 16) * H];  // conv2 segment sum (+sentinel row)
__device__ float g_hm[(MAXN + 16) * H];    // h1 @ W_msg2[:16]
__device__ int g_cnt[MAXN];                // histogram / scatter cursor
__device__ int g_bsum[512];                // scan block sums
__device__ int g_ssrc[MAXE];               // dst-sorted src
__device__ int g_sdst[MAXE];               // dst-sorted dst
__device__ int g_seid[MAXE];               // dst-sorted edge id

__device__ __forceinline__ void red_add_v4(float* addr, float a, float b, float c, float d) {
    asm volatile("red.global.add.v4.f32 [%0], {%1, %2, %3, %4};"
                 :: "l"(addr), "f"(a), "f"(b), "f"(c), "f"(d) : "memory");
}
__device__ __forceinline__ ull pack2(float lo, float hi) {
    ull r; asm("mov.b64 %0, {%1, %2};" : "=l"(r) : "f"(lo), "f"(hi)); return r;
}
__device__ __forceinline__ void unpack2(float& lo, float& hi, ull v) {
    asm("mov.b64 {%0, %1}, %2;" : "=f"(lo), "=f"(hi) : "l"(v));
}
__device__ __forceinline__ ull fma2(ull a, ull b, ull c) {
    ull d; asm("fma.rn.f32x2 %0, %1, %2, %3;" : "=l"(d) : "l"(a), "l"(b), "l"(c)); return d;
}
__device__ __forceinline__ ull add2(ull a, ull b) {
    ull d; asm("add.rn.f32x2 %0, %1, %2;" : "=l"(d) : "l"(a), "l"(b)); return d;
}

// ---------------------------------------------------------------------------
// Pass A: per node: xm = x @ Wm1[:64], sk1 = x @ Wsk1 + b ; zero agg1/agg2
// ---------------------------------------------------------------------------
__global__ void pass_a(const float* __restrict__ x,
                       const float* __restrict__ Wm1,
                       const float* __restrict__ Wsk1,
                       const float* __restrict__ bsk1,
                       int N) {
    __shared__ float sWm[D_IN * H];
    __shared__ float sWs[D_IN * H];
    __shared__ float sb[H];
    __shared__ float sx[16 * D_IN];
    int tid = threadIdx.x;
    for (int i = tid; i < D_IN * H; i += 256) { sWm[i] = Wm1[i]; sWs[i] = Wsk1[i]; }
    if (tid < H) sb[tid] = bsk1[tid];
    int nbase = blockIdx.x * 16;
    for (int i = tid; i < 16 * D_IN; i += 256) {
        int n = nbase + (i >> 6);
        sx[i] = (n < N) ? x[(size_t)n * D_IN + (i & 63)] : 0.f;
    }
    __syncthreads();
    int ln = tid >> 4, j = tid & 15;
    int n = nbase + ln;
    if (n >= N) return;
    const float* xr = &sx[ln * D_IN];
    float a = 0.f, s = sb[j];
#pragma unroll
    for (int k = 0; k < D_IN; k++) {
        float xv = xr[k];
        a = fmaf(xv, sWm[k * H + j], a);
        s = fmaf(xv, sWs[k * H + j], s);
    }
    int o = n * H + j;
    g_xm[o] = a;
    g_sk1[o] = s;
    g_agg1[o] = 0.f;
    g_agg2[o] = 0.f;
}

// ---------------------------------------------------------------------------
// Counting sort by dst
// ---------------------------------------------------------------------------
__global__ void k_zero(int N) {
    int i = blockIdx.x * 256 + threadIdx.x;
    if (i < N) g_cnt[i] = 0;
}
__global__ void k_hist(const int* __restrict__ ei, int E) {
    int e = blockIdx.x * 256 + threadIdx.x;
    if (e < E) atomicAdd(&g_cnt[ei[(size_t)E + e]], 1);
}
// block-level exclusive scan (512/block)
__global__ void k_scan1(int N) {
    __shared__ int s[2][512];
    int t = threadIdx.x;
    int i = blockIdx.x * 512 + t;
    int v = (i < N) ? g_cnt[i] : 0;
    s[0][t] = v;
    __syncthreads();
    int a = 0;
#pragma unroll
    for (int off = 1; off < 512; off <<= 1) {
        int src = a; a ^= 1;
        s[a][t] = s[src][t] + ((t >= off) ? s[src][t - off] : 0);
        __syncthreads();
    }
    int incl = s[a][t];
    if (i < N) g_cnt[i] = incl - v;  // local exclusive (reuse g_cnt as positions)
    if (t == 511) g_bsum[blockIdx.x] = incl;
}
__global__ void k_scan2(int nsb) {
    __shared__ int s[2][512];
    int t = threadIdx.x;
    int v = (t < nsb) ? g_bsum[t] : 0;
    s[0][t] = v;
    __syncthreads();
    int a = 0;
#pragma unroll
    for (int off = 1; off < 512; off <<= 1) {
        int src = a; a ^= 1;
        s[a][t] = s[src][t] + ((t >= off) ? s[src][t - off] : 0);
        __syncthreads();
    }
    if (t < nsb) g_bsum[t] = s[a][t] - v;  // exclusive
}
__global__ void k_scan3(int N) {
    int i = blockIdx.x * 256 + threadIdx.x;
    if (i < N) g_cnt[i] += g_bsum[i >> 9];
}
__global__ void k_scatter(const int* __restrict__ ei, int E) {
    int e = blockIdx.x * 256 + threadIdx.x;
    if (e >= E) return;
    int s = ei[e];
    int d = ei[(size_t)E + e];
    int p = atomicAdd(&g_cnt[d], 1);
    g_ssrc[p] = s;
    g_sdst[p] = d;
    g_seid[p] = e;
}

// ---------------------------------------------------------------------------
// Pass B (sorted): segmented accumulation of conv1 msg + conv2 edge part.
// 4 lanes per 16-edge chunk; lane c owns output dims [4c,4c+4) of m1 and m2.
// ---------------------------------------------------------------------------
__device__ __forceinline__ void flush_b(int node, int c, ull a0, ull a1, ull a2, ull a3,
                                        int cnt, ull B1L, ull B1H, ull B2L, ull B2H) {
    if (cnt == 0) return;
    float fc = (float)cnt;
    ull cp = pack2(fc, fc);
    a0 = fma2(cp, B1L, a0); a1 = fma2(cp, B1H, a1);
    a2 = fma2(cp, B2L, a2); a3 = fma2(cp, B2H, a3);
    float x0, x1, x2, x3;
    unpack2(x0, x1, a0); unpack2(x2, x3, a1);
    red_add_v4(&g_agg1[(size_t)node * H + c * 4], x0, x1, x2, x3);
    unpack2(x0, x1, a2); unpack2(x2, x3, a3);
    red_add_v4(&g_agg2[(size_t)node * H + c * 4], x0, x1, x2, x3);
}

__global__ void pass_b_sorted(const float* __restrict__ ea,
                              const float* __restrict__ Wm1,
                              const float* __restrict__ b1,
                              const float* __restrict__ Wm2,
                              const float* __restrict__ b2,
                              int N, int E) {
    __shared__ float sW[16 * 32];  // row k: [0..15]=Wm1[64+k], [16..31]=Wm2[16+k]
    __shared__ int s_src[1024], s_dst[1024], s_eid[1024];
    int tid = threadIdx.x;
    {
        int k = tid >> 4, j = tid & 15;
        sW[k * 32 + j]      = Wm1[(D_IN + k) * H + j];
        sW[k * 32 + 16 + j] = Wm2[(H + k) * H + j];
    }
    long eb = (long)blockIdx.x * 1024;
    for (int j = tid; j < 1024; j += 256) {
        long p = eb + j;
        if (p < E) { s_src[j] = g_ssrc[p]; s_dst[j] = g_sdst[p]; s_eid[j] = g_seid[p]; }
        else       { s_src[j] = 0; s_dst[j] = N; s_eid[j] = 0; }
    }
    __syncthreads();

    int g = tid >> 2, c = tid & 3, lane = tid & 31;
    int base = g * 16;
    float4 b1q = __ldg((const float4*)b1 + c);
    float4 b2q = __ldg((const float4*)b2 + c);
    ull B1L = pack2(b1q.x, b1q.y), B1H = pack2(b1q.z, b1q.w);
    ull B2L = pack2(b2q.x, b2q.y), B2H = pack2(b2q.z, b2q.w);

    ull a0 = 0, a1 = 0, a2 = 0, a3 = 0;
    int cnt = 0;
    int cur = s_dst[base];
    const ull* wr = (const ull*)sW;  // 16 ull per row

#pragma unroll 1
    for (int i = 0; i < 16; i++) {
        int idx = base + i;
        int d = s_dst[idx];
        int src = s_src[idx];
        int eid = s_eid[idx];
        if (d != cur) {
            flush_b(cur, c, a0, a1, a2, a3, cnt, B1L, B1H, B2L, B2H);
            a0 = a1 = a2 = a3 = 0ULL; cnt = 0; cur = d;
        }
        float4 v  = __ldg((const float4*)ea + (size_t)eid * 4 + c);
        float4 xv = __ldg((const float4*)g_xm + (size_t)src * 4 + c);
        a0 = add2(a0, pack2(xv.x, xv.y));
        a1 = add2(a1, pack2(xv.z, xv.w));
        cnt++;
#pragma unroll
        for (int k = 0; k < 16; k++) {
            float comp = ((k & 3) == 0) ? v.x : ((k & 3) == 1) ? v.y : ((k & 3) == 2) ? v.z : v.w;
            float ev = __shfl_sync(0xffffffffu, comp, (lane & ~3) | (k >> 2), 32);
            ull evp = pack2(ev, ev);
            ull w0 = wr[k * 16 + 2 * c];
            ull w1 = wr[k * 16 + 2 * c + 1];
            ull w2 = wr[k * 16 + 8 + 2 * c];
            ull w3 = wr[k * 16 + 8 + 2 * c + 1];
            a0 = fma2(evp, w0, a0);
            a1 = fma2(evp, w1, a1);
            a2 = fma2(evp, w2, a2);
            a3 = fma2(evp, w3, a3);
        }
    }
    flush_b(cur, c, a0, a1, a2, a3, cnt, B1L, B1H, B2L, B2H);
}

// ---------------------------------------------------------------------------
// Pass C: h1 = relu(agg1 + sk1); hm = h1 @ Wm2[:16]; agg2 += h1 @ Wsk2 + b
// ---------------------------------------------------------------------------
__global__ void pass_c(const float* __restrict__ Wm2,
                       const float* __restrict__ Wsk2,
                       const float* __restrict__ bsk2,
                       int N) {
    __shared__ float sWm[H * H];
    __shared__ float sWs[H * H];
    __shared__ float sb[H];
    __shared__ float sh[16 * 17];
    int tid = threadIdx.x;
    sWm[tid] = Wm2[tid];
    sWs[tid] = Wsk2[tid];
    if (tid < H) sb[tid] = bsk2[tid];
    int ln = tid >> 4, j = tid & 15;
    int n = blockIdx.x * 16 + ln;
    float h = 0.f;
    if (n < N) {
        int o = n * H + j;
        h = fmaxf(g_agg1[o] + g_sk1[o], 0.f);
    }
    sh[ln * 17 + j] = h;
    __syncthreads();
    if (n >= N) return;
    const float* hr = &sh[ln * 17];
    float hm = 0.f, sk = sb[j];
#pragma unroll
    for (int k = 0; k < H; k++) {
        float hv = hr[k];
        hm = fmaf(hv, sWm[k * H + j], hm);
        sk = fmaf(hv, sWs[k * H + j], sk);
    }
    int o = n * H + j;
    g_hm[o] = hm;
    g_agg2[o] += sk;
}

// ---------------------------------------------------------------------------
// Pass D (sorted): agg2[dst] += hm[src], segmented, 32-edge chunks per group
// ---------------------------------------------------------------------------
__global__ void pass_d_sorted(int N, int E) {
    __shared__ int s_src[2048], s_dst[2048];
    int tid = threadIdx.x;
    long eb = (long)blockIdx.x * 2048;
    for (int j = tid; j < 2048; j += 256) {
        long p = eb + j;
        if (p < E) { s_src[j] = g_ssrc[p]; s_dst[j] = g_sdst[p]; }
        else       { s_src[j] = 0; s_dst[j] = N; }
    }
    __syncthreads();
    int g = tid >> 2, c = tid & 3;
    int base = g * 32;
    float ax = 0.f, ay = 0.f, az = 0.f, aw = 0.f;
    int cnt = 0;
    int cur = s_dst[base];
#pragma unroll 1
    for (int i = 0; i < 32; i++) {
        int idx = base + i;
        int d = s_dst[idx];
        int src = s_src[idx];
        if (d != cur) {
            if (cnt) red_add_v4(&g_agg2[(size_t)cur * H + c * 4], ax, ay, az, aw);
            ax = ay = az = aw = 0.f; cnt = 0; cur = d;
        }
        float4 hv = __ldg((const float4*)g_hm + (size_t)src * 4 + c);
        ax += hv.x; ay += hv.y; az += hv.z; aw += hv.w;
        cnt++;
    }
    if (cnt) red_add_v4(&g_agg2[(size_t)cur * H + c * 4], ax, ay, az, aw);
}

// ---------------------------------------------------------------------------
// Pass E: out = agg2 @ Wl3 + bl3
// ---------------------------------------------------------------------------
__global__ void pass_e(const float* __restrict__ Wl3,
                       const float* __restrict__ bl3,
                       float* __restrict__ out, int N) {
    __shared__ float sW[H * D_IN];
    __shared__ float sb[D_IN];
    int tid = threadIdx.x;
    for (int i = tid; i < H * D_IN; i += 256) sW[i] = Wl3[i];
    if (tid < D_IN) sb[tid] = bl3[tid];
    __syncthreads();
    int ln = tid >> 6, d = tid & 63;
    int n = blockIdx.x * 4 + ln;
    if (n >= N) return;
    const float* h2 = &g_agg2[(size_t)n * H];
    float acc = sb[d];
#pragma unroll
    for (int k = 0; k < H; k++) acc = fmaf(__ldg(&h2[k]), sW[k * D_IN + d], acc);
    out[(size_t)n * D_IN + d] = acc;
}

// ---------------------------------------------------------------------------
extern "C" void kernel_launch(void* const* d_in, const int* in_sizes, int n_in,
                              void* d_out, int out_size) {
    const float* x    = (const float*)d_in[0];
    const int*   ei   = (const int*)d_in[1];
    const float* ea   = (const float*)d_in[2];
    const float* Wm1  = (const float*)d_in[3];
    const float* bm1  = (const float*)d_in[4];
    const float* Wsk1 = (const float*)d_in[5];
    const float* bsk1 = (const float*)d_in[6];
    const float* Wm2  = (const float*)d_in[7];
    const float* bm2  = (const float*)d_in[8];
    const float* Wsk2 = (const float*)d_in[9];
    const float* bsk2 = (const float*)d_in[10];
    const float* Wl3  = (const float*)d_in[11];
    const float* bl3  = (const float*)d_in[12];
    float* out = (float*)d_out;

    int N = in_sizes[0] / D_IN;
    int E = in_sizes[1] / 2;

    int nb16 = (N + 15) / 16;
    int ebl  = (E + 255) / 256;
    int nsb  = (N + 511) / 512;

    k_zero<<<(N + 255) / 256, 256>>>(N);
    pass_a<<<nb16, 256>>>(x, Wm1, Wsk1, bsk1, N);
    k_hist<<<ebl, 256>>>(ei, E);
    k_scan1<<<nsb, 512>>>(N);
    k_scan2<<<1, 512>>>(nsb);
    k_scan3<<<(N + 255) / 256, 256>>>(N);
    k_scatter<<<ebl, 256>>>(ei, E);
    pass_b_sorted<<<(E + 1023) / 1024, 256>>>(ea, Wm1, bm1, Wm2, bm2, N, E);
    pass_c<<<nb16, 256>>>(Wm2, Wsk2, bsk2, N);
    pass_d_sorted<<<(E + 2047) / 2048, 256>>>(N, E);
    pass_e<<<(N + 3) / 4, 256>>>(Wl3, bl3, out, N);
}

// round 4
// speedup vs baseline: 1.8129x; 1.8129x over previous
#include <cuda_runtime.h>
#include <cstdint>

#define D_IN 64
#define D_EDGE 16
#define H 16
#define MAXN 102400
#define MAXE 3276800

// ---------------- static device scratch ----------------
__device__ float g_xm[MAXN * H + 64];    // x @ W_msg1[:64]
__device__ float g_sk1[MAXN * H + 64];   // x @ W_skip1 + b_skip1
__device__ float g_hm[MAXN * H + 64];    // h1 @ W_msg2[:16]
__device__ float g_agg2[MAXN * H + 64];  // conv2 partial (edge-const + skip2)
__device__ int   g_rowp[MAXN + 1];       // CSR row offsets (by dst)
__device__ int   g_cur[MAXN];            // histogram / scatter cursor
__device__ int   g_bsum[512];            // scan block sums
__device__ int2  g_se[MAXE];             // dst-sorted (src, eid)

// ---------------------------------------------------------------------------
// Pass A: per node: xm = x @ Wm1[:64], sk1 = x @ Wsk1 + b_sk1
// ---------------------------------------------------------------------------
__global__ void pass_a(const float* __restrict__ x,
                       const float* __restrict__ Wm1,
                       const float* __restrict__ Wsk1,
                       const float* __restrict__ bsk1,
                       int N) {
    __shared__ float sWm[D_IN * H];
    __shared__ float sWs[D_IN * H];
    __shared__ float sb[H];
    __shared__ float sx[16 * D_IN];
    int tid = threadIdx.x;
    for (int i = tid; i < D_IN * H; i += 256) { sWm[i] = Wm1[i]; sWs[i] = Wsk1[i]; }
    if (tid < H) sb[tid] = bsk1[tid];
    int nbase = blockIdx.x * 16;
    for (int i = tid; i < 16 * D_IN; i += 256) {
        int n = nbase + (i >> 6);
        sx[i] = (n < N) ? x[(size_t)n * D_IN + (i & 63)] : 0.f;
    }
    __syncthreads();
    int ln = tid >> 4, j = tid & 15;
    int n = nbase + ln;
    if (n >= N) return;
    const float* xr = &sx[ln * D_IN];
    float a = 0.f, s = sb[j];
#pragma unroll
    for (int k = 0; k < D_IN; k++) {
        float xv = xr[k];
        a = fmaf(xv, sWm[k * H + j], a);
        s = fmaf(xv, sWs[k * H + j], s);
    }
    int o = n * H + j;
    g_xm[o] = a;
    g_sk1[o] = s;
}

// ---------------------------------------------------------------------------
// Counting sort by dst -> CSR
// ---------------------------------------------------------------------------
__global__ void k_zero(int N) {
    int i = blockIdx.x * 256 + threadIdx.x;
    if (i < N) g_cur[i] = 0;
}
__global__ void k_hist(const int* __restrict__ ei, int E) {
    int e = blockIdx.x * 256 + threadIdx.x;
    if (e < E) atomicAdd(&g_cur[ei[(size_t)E + e]], 1);
}
__global__ void k_scan1(int N) {
    __shared__ int s[2][512];
    int t = threadIdx.x;
    int i = blockIdx.x * 512 + t;
    int v = (i < N) ? g_cur[i] : 0;
    s[0][t] = v;
    __syncthreads();
    int a = 0;
#pragma unroll
    for (int off = 1; off < 512; off <<= 1) {
        int sr = a; a ^= 1;
        s[a][t] = s[sr][t] + ((t >= off) ? s[sr][t - off] : 0);
        __syncthreads();
    }
    int incl = s[a][t];
    if (i < N) g_cur[i] = incl - v;  // local exclusive
    if (t == 511) g_bsum[blockIdx.x] = incl;
}
__global__ void k_scan2(int nsb) {
    __shared__ int s[2][512];
    int t = threadIdx.x;
    int v = (t < nsb) ? g_bsum[t] : 0;
    s[0][t] = v;
    __syncthreads();
    int a = 0;
#pragma unroll
    for (int off = 1; off < 512; off <<= 1) {
        int sr = a; a ^= 1;
        s[a][t] = s[sr][t] + ((t >= off) ? s[sr][t - off] : 0);
        __syncthreads();
    }
    if (t < nsb) g_bsum[t] = s[a][t] - v;  // exclusive
}
__global__ void k_scan3(int N, int E) {
    int i = blockIdx.x * 256 + threadIdx.x;
    if (i < N) {
        int v = g_cur[i] + g_bsum[i >> 9];
        g_cur[i] = v;
        g_rowp[i] = v;
    } else if (i == N) {
        g_rowp[N] = E;
    }
}
__global__ void k_scatter(const int* __restrict__ ei, int E) {
    int e = blockIdx.x * 256 + threadIdx.x;
    if (e >= E) return;
    int s = ei[e];
    int d = ei[(size_t)E + e];
    int p = atomicAdd(&g_cur[d], 1);
    g_se[p] = make_int2(s, e);
}

// ---------------------------------------------------------------------------
// Pass BC (fused conv1 + inter-layer): one warp per node.
//   S_x = sum xm[src], S_e = sum ea[eid] over incoming edges (CSR pull)
//   agg1 = S_x + S_e@W1e + deg*b1 + sk1 ; h1 = relu(agg1)
//   hm   = h1@Wm2[:16]
//   agg2 = S_e@W2e + deg*b2 + h1@Wsk2 + bsk2
// lanes: eslot = lane>>2 (8 parallel edges), c = lane&3 (float4 quarter)
// ---------------------------------------------------------------------------
__global__ void pass_bc(const float* __restrict__ ea,
                        const float* __restrict__ Wm1,
                        const float* __restrict__ b1,
                        const float* __restrict__ Wm2,
                        const float* __restrict__ b2,
                        const float* __restrict__ Wsk2,
                        const float* __restrict__ bsk2,
                        int N) {
    __shared__ float sW1e[H * H];   // Wm1 rows 64..79
    __shared__ float sW2e[H * H];   // Wm2 rows 16..31
    __shared__ float sWm2[H * H];   // Wm2 rows 0..15
    __shared__ float sWs2[H * H];   // Wsk2
    __shared__ float sb1[H], sb2[H], sbs2[H];
    __shared__ float sS[8][48];     // per warp: Sx[0:16) Se[16:32) h1[32:48)
    int tid = threadIdx.x;
    sW1e[tid] = Wm1[D_IN * H + tid];
    sWm2[tid] = Wm2[tid];
    sW2e[tid] = Wm2[H * H + tid];
    sWs2[tid] = Wsk2[tid];
    if (tid < H) { sb1[tid] = b1[tid]; sb2[tid] = b2[tid]; sbs2[tid] = bsk2[tid]; }
    __syncthreads();

    int w = tid >> 5, lane = tid & 31;
    int n = blockIdx.x * 8 + w;
    if (n >= N) return;
    int r0 = g_rowp[n], r1 = g_rowp[n + 1];
    int eslot = lane >> 2, c = lane & 3;

    float ax0 = 0.f, ax1 = 0.f, ax2 = 0.f, ax3 = 0.f;
    float ae0 = 0.f, ae1 = 0.f, ae2 = 0.f, ae3 = 0.f;
    for (int p = r0 + eslot; p < r1; p += 8) {
        int2 se = g_se[p];
        float4 e4 = __ldg((const float4*)ea + (size_t)se.y * 4 + c);
        float4 x4 = *((const float4*)g_xm + (size_t)se.x * 4 + c);
        ax0 += x4.x; ax1 += x4.y; ax2 += x4.z; ax3 += x4.w;
        ae0 += e4.x; ae1 += e4.y; ae2 += e4.z; ae3 += e4.w;
    }
#pragma unroll
    for (int off = 4; off < 32; off <<= 1) {
        ax0 += __shfl_xor_sync(0xffffffffu, ax0, off);
        ax1 += __shfl_xor_sync(0xffffffffu, ax1, off);
        ax2 += __shfl_xor_sync(0xffffffffu, ax2, off);
        ax3 += __shfl_xor_sync(0xffffffffu, ax3, off);
        ae0 += __shfl_xor_sync(0xffffffffu, ae0, off);
        ae1 += __shfl_xor_sync(0xffffffffu, ae1, off);
        ae2 += __shfl_xor_sync(0xffffffffu, ae2, off);
        ae3 += __shfl_xor_sync(0xffffffffu, ae3, off);
    }
    if (eslot == 0) {
        float* S = sS[w];
        S[c * 4 + 0] = ax0; S[c * 4 + 1] = ax1; S[c * 4 + 2] = ax2; S[c * 4 + 3] = ax3;
        S[16 + c * 4 + 0] = ae0; S[16 + c * 4 + 1] = ae1; S[16 + c * 4 + 2] = ae2; S[16 + c * 4 + 3] = ae3;
    }
    __syncwarp();

    float deg = (float)(r1 - r0);
    if (lane < 16) {
        int j = lane;
        float a = sS[w][j] + deg * sb1[j] + g_sk1[n * H + j];
#pragma unroll
        for (int k = 0; k < H; k++) a = fmaf(sS[w][16 + k], sW1e[k * H + j], a);
        sS[w][32 + j] = fmaxf(a, 0.f);
    }
    __syncwarp();
    if (lane < 16) {
        int j = lane;
        float hm = 0.f;
        float a2 = deg * sb2[j] + sbs2[j];
#pragma unroll
        for (int k = 0; k < H; k++) {
            float hk = sS[w][32 + k];
            hm = fmaf(hk, sWm2[k * H + j], hm);
            a2 = fmaf(hk, sWs2[k * H + j], a2);
            a2 = fmaf(sS[w][16 + k], sW2e[k * H + j], a2);
        }
        g_hm[n * H + j] = hm;
        g_agg2[n * H + j] = a2;
    }
}

// ---------------------------------------------------------------------------
// Pass DE (fused conv2-aggregate + lin3): one warp per node.
//   h2 = agg2 + sum hm[src] ; out = h2 @ Wl3 + bl3
// ---------------------------------------------------------------------------
__global__ void pass_de(const float* __restrict__ Wl3,
                        const float* __restrict__ bl3,
                        float* __restrict__ out, int N) {
    __shared__ float sW[H * D_IN];
    __shared__ float sb[D_IN];
    __shared__ float sH[8][20];
    int tid = threadIdx.x;
    for (int i = tid; i < H * D_IN; i += 256) sW[i] = Wl3[i];
    if (tid < D_IN) sb[tid] = bl3[tid];
    __syncthreads();

    int w = tid >> 5, lane = tid & 31;
    int n = blockIdx.x * 8 + w;
    if (n >= N) return;
    int r0 = g_rowp[n], r1 = g_rowp[n + 1];
    int eslot = lane >> 2, c = lane & 3;

    float a0 = 0.f, a1 = 0.f, a2 = 0.f, a3 = 0.f;
    for (int p = r0 + eslot; p < r1; p += 8) {
        int src = g_se[p].x;
        float4 h4 = *((const float4*)g_hm + (size_t)src * 4 + c);
        a0 += h4.x; a1 += h4.y; a2 += h4.z; a3 += h4.w;
    }
#pragma unroll
    for (int off = 4; off < 32; off <<= 1) {
        a0 += __shfl_xor_sync(0xffffffffu, a0, off);
        a1 += __shfl_xor_sync(0xffffffffu, a1, off);
        a2 += __shfl_xor_sync(0xffffffffu, a2, off);
        a3 += __shfl_xor_sync(0xffffffffu, a3, off);
    }
    if (eslot == 0) {
        int b = c * 4;
        const float* ag = &g_agg2[n * H];
        sH[w][b + 0] = a0 + ag[b + 0];
        sH[w][b + 1] = a1 + ag[b + 1];
        sH[w][b + 2] = a2 + ag[b + 2];
        sH[w][b + 3] = a3 + ag[b + 3];
    }
    __syncwarp();

    float acc0 = sb[lane], acc1 = sb[lane + 32];
#pragma unroll
    for (int k = 0; k < H; k++) {
        float hk = sH[w][k];
        acc0 = fmaf(hk, sW[k * D_IN + lane], acc0);
        acc1 = fmaf(hk, sW[k * D_IN + lane + 32], acc1);
    }
    out[(size_t)n * D_IN + lane] = acc0;
    out[(size_t)n * D_IN + lane + 32] = acc1;
}

// ---------------------------------------------------------------------------
extern "C" void kernel_launch(void* const* d_in, const int* in_sizes, int n_in,
                              void* d_out, int out_size) {
    const float* x    = (const float*)d_in[0];
    const int*   ei   = (const int*)d_in[1];
    const float* ea   = (const float*)d_in[2];
    const float* Wm1  = (const float*)d_in[3];
    const float* bm1  = (const float*)d_in[4];
    const float* Wsk1 = (const float*)d_in[5];
    const float* bsk1 = (const float*)d_in[6];
    const float* Wm2  = (const float*)d_in[7];
    const float* bm2  = (const float*)d_in[8];
    const float* Wsk2 = (const float*)d_in[9];
    const float* bsk2 = (const float*)d_in[10];
    const float* Wl3  = (const float*)d_in[11];
    const float* bl3  = (const float*)d_in[12];
    float* out = (float*)d_out;

    int N = in_sizes[0] / D_IN;
    int E = in_sizes[1] / 2;

    int ebl = (E + 255) / 256;
    int nsb = (N + 511) / 512;

    k_zero<<<(N + 255) / 256, 256>>>(N);
    pass_a<<<(N + 15) / 16, 256>>>(x, Wm1, Wsk1, bsk1, N);
    k_hist<<<ebl, 256>>>(ei, E);
    k_scan1<<<nsb, 512>>>(N);
    k_scan2<<<1, 512>>>(nsb);
    k_scan3<<<(N + 256) / 256, 256>>>(N, E);
    k_scatter<<<ebl, 256>>>(ei, E);
    pass_bc<<<(N + 7) / 8, 256>>>(ea, Wm1, bm1, Wm2, bm2, Wsk2, bsk2, N);
    pass_de<<<(N + 7) / 8, 256>>>(Wl3, bl3, out, N);
}